// round 4
// baseline (speedup 1.0000x reference)
#include <cuda_runtime.h>
#include <cuda_bf16.h>
#include <math.h>

#define NMAX 100000
#define EMAX 500000
#define AST 132      // As stride (words)
#define BST 72       // Bs k-major stride (words)

// ---------------- scratch ----------------------------------------------------
__device__ __align__(16) __nv_bfloat16 g_XAB[(size_t)NMAX * 768]; // [XA|XB] bf16
__device__ __align__(16) float g_H[(size_t)NMAX * 128];           // relu(x@W1+b1)
__device__ float g_signal[NMAX];
__device__ int   g_elist[EMAX];
__device__ int   g_ecount;
__device__ int   g_idx64;

// ---------------- helpers -----------------------------------------------------
__device__ __forceinline__ unsigned f2tf(float f) {
    unsigned u; asm("cvt.rna.tf32.f32 %0, %1;" : "=r"(u) : "f"(f)); return u;
}
__device__ __forceinline__ void mma8(float* c, unsigned a0, unsigned a1,
                                     unsigned a2, unsigned a3,
                                     unsigned b0, unsigned b1) {
    asm volatile(
        "mma.sync.aligned.m16n8k8.row.col.f32.tf32.tf32.f32 "
        "{%0,%1,%2,%3},{%4,%5,%6,%7},{%8,%9},{%0,%1,%2,%3};"
        : "+f"(c[0]), "+f"(c[1]), "+f"(c[2]), "+f"(c[3])
        : "r"(a0), "r"(a1), "r"(a2), "r"(a3), "r"(b0), "r"(b1));
}
__device__ __forceinline__ void cp16(void* sdst, const void* gsrc) {
    unsigned s = (unsigned)__cvta_generic_to_shared(sdst);
    asm volatile("cp.async.cg.shared.global [%0], [%1], 16;\n" :: "r"(s), "l"(gsrc));
}
__device__ __forceinline__ void cp_commit() { asm volatile("cp.async.commit_group;\n" ::); }
__device__ __forceinline__ void cp_wait0()  { asm volatile("cp.async.wait_group 0;\n" ::); }
__device__ __forceinline__ void cp_wait1()  { asm volatile("cp.async.wait_group 1;\n" ::); }

// ---------------- init / compact ---------------------------------------------
__global__ void init_kernel(int N, const int* __restrict__ ei_raw) {
    int i = blockIdx.x * blockDim.x + threadIdx.x;
    if (i == 0) {
        g_ecount = 0;
        int allz = 1;
        #pragma unroll
        for (int j = 1; j < 64; j += 2)
            if (ei_raw[j] != 0) { allz = 0; break; }
        g_idx64 = allz;
    }
    if (i < N) g_signal[i] = 0.0f;
}

__global__ void compact_kernel(const int* __restrict__ ei, int E,
                               const int* __restrict__ bs_ptr) {
    int e = blockIdx.x * blockDim.x + threadIdx.x;
    if (e >= E) return;
    int bs  = *bs_ptr;
    int src = g_idx64 ? ei[2 * e] : ei[e];
    if (src < bs) {
        int p = atomicAdd(&g_ecount, 1);
        g_elist[p] = e;
    }
}

// ---------------- fused x-GEMM: x @ [V1a | V1b | W1], M=128 tiles ------------
__global__ __launch_bounds__(256) void xgemm_mma(
    const float* __restrict__ x, const float* __restrict__ V1,
    const float* __restrict__ W1, const float* __restrict__ b1,
    int N, const int* __restrict__ bs_ptr)
{
    extern __shared__ float fsm[];
    float* Asf = fsm;                 // [128][AST]
    float* Bsf = fsm + 128 * AST;     // [128][BST] k-major

    int bs = *bs_ptr; if (bs > N) bs = N;
    int ct = blockIdx.y;
    int limit = (ct >= 6 && ct < 12) ? N : bs;
    int row0 = blockIdx.x * 128;
    if (row0 >= limit) return;
    int ne = min(128, limit - row0);
    int t = threadIdx.x;

    for (int i = t; i < 128 * 32; i += 256) {
        int r = i >> 5, c4 = i & 31;
        int rs = (r < ne) ? (row0 + r) : row0;
        cp16(&Asf[r * AST + c4 * 4], x + (size_t)rs * 128 + c4 * 4);
    }
    const float* Bsrc; int sb, koff, n0;
    if (ct < 6)       { Bsrc = V1; sb = 384; koff = 0;   n0 = ct * 64; }
    else if (ct < 12) { Bsrc = V1; sb = 384; koff = 128; n0 = (ct - 6) * 64; }
    else              { Bsrc = W1; sb = 128; koff = 0;   n0 = (ct - 12) * 64; }
    for (int i = t; i < 2048; i += 256) {
        int k = i >> 4, n4 = i & 15;
        cp16(&Bsf[k * BST + n4 * 4], Bsrc + (size_t)(koff + k) * sb + n0 + n4 * 4);
    }
    cp_commit();
    cp_wait0();
    __syncthreads();

    int lane = t & 31, w = t >> 5;
    int wm = w >> 1, wn = w & 1;            // 4 x 2 warps, tile 32x32
    int g = lane >> 2, t4 = lane & 3;
    float C[2][4][4] = {};

    #pragma unroll
    for (int k0 = 0; k0 < 128; k0 += 8) {
        unsigned a[2][4], b[4][2];
        #pragma unroll
        for (int mi = 0; mi < 2; mi++) {
            int rb = wm * 32 + mi * 16;
            a[mi][0] = f2tf(Asf[(rb + g)     * AST + k0 + t4]);
            a[mi][1] = f2tf(Asf[(rb + g + 8) * AST + k0 + t4]);
            a[mi][2] = f2tf(Asf[(rb + g)     * AST + k0 + t4 + 4]);
            a[mi][3] = f2tf(Asf[(rb + g + 8) * AST + k0 + t4 + 4]);
        }
        #pragma unroll
        for (int ni = 0; ni < 4; ni++) {
            int nb = wn * 32 + ni * 8 + g;
            b[ni][0] = f2tf(Bsf[(k0 + t4)     * BST + nb]);
            b[ni][1] = f2tf(Bsf[(k0 + t4 + 4) * BST + nb]);
        }
        #pragma unroll
        for (int mi = 0; mi < 2; mi++)
            #pragma unroll
            for (int ni = 0; ni < 4; ni++)
                mma8(C[mi][ni], a[mi][0], a[mi][1], a[mi][2], a[mi][3],
                     b[ni][0], b[ni][1]);
    }

    bool isH = (ct >= 12);
    #pragma unroll
    for (int mi = 0; mi < 2; mi++)
        #pragma unroll
        for (int ni = 0; ni < 4; ni++) {
            int ncl = wn * 32 + ni * 8 + 2 * t4;
            #pragma unroll
            for (int half = 0; half < 2; half++) {
                int r = wm * 32 + mi * 16 + g + half * 8;
                if (r < ne) {
                    float v0 = C[mi][ni][half * 2 + 0];
                    float v1 = C[mi][ni][half * 2 + 1];
                    size_t row = row0 + r;
                    if (isH) {
                        int jg = (ct - 12) * 64 + ncl;
                        float2 o;
                        o.x = fmaxf(v0 + b1[jg],     0.f);
                        o.y = fmaxf(v1 + b1[jg + 1], 0.f);
                        *(float2*)(g_H + row * 128 + jg) = o;
                    } else {
                        int jg = ct * 64 + ncl;
                        __nv_bfloat162 o = __floats2bfloat162_rn(v0, v1);
                        *reinterpret_cast<__nv_bfloat162*>(g_XAB + row * 768 + jg) = o;
                    }
                }
            }
        }
}

// ---------------- edge kernel: 128 edges/block, chunked pipeline -------------
__global__ __launch_bounds__(256, 2) void edge_mma(
    const float* __restrict__ edge_attr, const float* __restrict__ V1,
    const float* __restrict__ bv1, const float* __restrict__ V2,
    const float* __restrict__ bv2, const int* __restrict__ ei, int E)
{
    extern __shared__ unsigned dsm[];
    unsigned* As = dsm;                        // [128][AST] tf32 (persistent)
    float* Bb0 = (float*)(dsm + 128 * AST);    // [64][BST] chunk buffers
    float* Bb1 = Bb0 + 64 * BST;

    __shared__ int s_src[128], s_dst[128], s_eid[128];
    __shared__ float s_part[128 * 2];

    int cnt = g_ecount;
    int base = blockIdx.x * 128;
    if (base >= cnt) return;
    int ne = min(128, cnt - base);
    int t = threadIdx.x;
    int i64 = g_idx64;

    if (t < 128) {
        int e = 0, ss = 0, dd = 0;
        if (t < ne) {
            e  = g_elist[base + t];
            ss = i64 ? ei[2 * e]       : ei[e];
            dd = i64 ? ei[2 * (E + e)] : ei[E + e];
        }
        s_eid[t] = e; s_src[t] = ss; s_dst[t] = dd;
    }
    s_part[t] = 0.f;
    __syncthreads();

    // kick off chunk (ct=0, kc=0) into Bb0
    for (int i = t; i < 1024; i += 256) {
        int k = i >> 4, n4 = i & 15;
        cp16(&Bb0[k * BST + n4 * 4], V1 + (size_t)(256 + k) * 384 + n4 * 4);
    }
    cp_commit();

    // As fill: gathered edge_attr rows, converted to tf32 once
    for (int i = t; i < 128 * 32; i += 256) {
        int r = i >> 5, c4 = i & 31;
        float4 v = *(const float4*)(edge_attr + (size_t)s_eid[r] * 128 + c4 * 4);
        unsigned* p = &As[r * AST + c4 * 4];
        p[0] = f2tf(v.x); p[1] = f2tf(v.y); p[2] = f2tf(v.z); p[3] = f2tf(v.w);
    }

    int lane = t & 31, w = t >> 5;
    int wm = w >> 1, wn = w & 1;           // 4 x 2 warps, tile 32x32
    int g = lane >> 2, t4 = lane & 3;
    float psc[2][2] = {};

    #pragma unroll 1
    for (int ct = 0; ct < 6; ++ct) {
        // ---- phase 0: k = 0..63 from Bb0; prefetch (ct,1) into Bb1 ----
        __syncthreads();                               // Bb1 readers (prev ct) done
        for (int i = t; i < 1024; i += 256) {
            int k = i >> 4, n4 = i & 15;
            cp16(&Bb1[k * BST + n4 * 4],
                 V1 + (size_t)(256 + 64 + k) * 384 + ct * 64 + n4 * 4);
        }
        cp_commit();
        cp_wait1();                                    // chunk (ct,0) ready
        __syncthreads();

        // prefetch bf16 XA/XB epilogue values for this ct
        unsigned pxa[2][2][4], pxb[2][2][4];
        #pragma unroll
        for (int mi = 0; mi < 2; mi++)
            #pragma unroll
            for (int half = 0; half < 2; half++) {
                int r = wm * 32 + mi * 16 + g + half * 8;
                const __nv_bfloat16* pa = g_XAB + (size_t)s_src[r] * 768 + ct * 64;
                const __nv_bfloat16* pb = g_XAB + (size_t)s_dst[r] * 768 + 384 + ct * 64;
                #pragma unroll
                for (int ni = 0; ni < 4; ni++) {
                    int ncl = wn * 32 + ni * 8 + 2 * t4;
                    pxa[mi][half][ni] = *reinterpret_cast<const unsigned*>(pa + ncl);
                    pxb[mi][half][ni] = *reinterpret_cast<const unsigned*>(pb + ncl);
                }
            }

        float C[2][4][4] = {};
        #pragma unroll
        for (int lk = 0; lk < 64; lk += 8) {
            unsigned a[2][4], b[4][2];
            #pragma unroll
            for (int mi = 0; mi < 2; mi++) {
                int rb = wm * 32 + mi * 16;
                a[mi][0] = As[(rb + g)     * AST + lk + t4];
                a[mi][1] = As[(rb + g + 8) * AST + lk + t4];
                a[mi][2] = As[(rb + g)     * AST + lk + t4 + 4];
                a[mi][3] = As[(rb + g + 8) * AST + lk + t4 + 4];
            }
            #pragma unroll
            for (int ni = 0; ni < 4; ni++) {
                int nb = wn * 32 + ni * 8 + g;
                b[ni][0] = f2tf(Bb0[(lk + t4)     * BST + nb]);
                b[ni][1] = f2tf(Bb0[(lk + t4 + 4) * BST + nb]);
            }
            #pragma unroll
            for (int mi = 0; mi < 2; mi++)
                #pragma unroll
                for (int ni = 0; ni < 4; ni++)
                    mma8(C[mi][ni], a[mi][0], a[mi][1], a[mi][2], a[mi][3],
                         b[ni][0], b[ni][1]);
        }

        // ---- phase 1: k = 64..127 from Bb1; prefetch (ct+1,0) into Bb0 ----
        __syncthreads();                               // Bb0 readers done
        if (ct < 5) {
            for (int i = t; i < 1024; i += 256) {
                int k = i >> 4, n4 = i & 15;
                cp16(&Bb0[k * BST + n4 * 4],
                     V1 + (size_t)(256 + k) * 384 + (ct + 1) * 64 + n4 * 4);
            }
        }
        cp_commit();
        cp_wait1();                                    // chunk (ct,1) ready
        __syncthreads();

        #pragma unroll
        for (int lk = 0; lk < 64; lk += 8) {
            unsigned a[2][4], b[4][2];
            #pragma unroll
            for (int mi = 0; mi < 2; mi++) {
                int rb = wm * 32 + mi * 16;
                a[mi][0] = As[(rb + g)     * AST + 64 + lk + t4];
                a[mi][1] = As[(rb + g + 8) * AST + 64 + lk + t4];
                a[mi][2] = As[(rb + g)     * AST + 64 + lk + t4 + 4];
                a[mi][3] = As[(rb + g + 8) * AST + 64 + lk + t4 + 4];
            }
            #pragma unroll
            for (int ni = 0; ni < 4; ni++) {
                int nb = wn * 32 + ni * 8 + g;
                b[ni][0] = f2tf(Bb1[(lk + t4)     * BST + nb]);
                b[ni][1] = f2tf(Bb1[(lk + t4 + 4) * BST + nb]);
            }
            #pragma unroll
            for (int mi = 0; mi < 2; mi++)
                #pragma unroll
                for (int ni = 0; ni < 4; ni++)
                    mma8(C[mi][ni], a[mi][0], a[mi][1], a[mi][2], a[mi][3],
                         b[ni][0], b[ni][1]);
        }

        // ---- epilogue for this ct ----
        #pragma unroll
        for (int mi = 0; mi < 2; mi++)
            #pragma unroll
            for (int half = 0; half < 2; half++) {
                int r = wm * 32 + mi * 16 + g + half * 8;
                if (r < ne) {
                    #pragma unroll
                    for (int ni = 0; ni < 4; ni++) {
                        int ncl = wn * 32 + ni * 8 + 2 * t4;
                        int jg  = ct * 64 + ncl;
                        float2 bv = *(const float2*)(bv1 + jg);
                        float2 v2 = *(const float2*)(V2 + jg);
                        float2 fa = __bfloat1622float2(
                            *reinterpret_cast<__nv_bfloat162*>(&pxa[mi][half][ni]));
                        float2 fb = __bfloat1622float2(
                            *reinterpret_cast<__nv_bfloat162*>(&pxb[mi][half][ni]));
                        float h0 = fmaxf(C[mi][ni][half * 2 + 0] + fa.x + fb.x + bv.x, 0.f);
                        float h1 = fmaxf(C[mi][ni][half * 2 + 1] + fa.y + fb.y + bv.y, 0.f);
                        psc[mi][half] += h0 * v2.x + h1 * v2.y;
                    }
                }
            }
    }

    // deterministic per-edge reduction: shfl over t4, then 2 warp_n partials
    #pragma unroll
    for (int mi = 0; mi < 2; mi++)
        #pragma unroll
        for (int half = 0; half < 2; half++) {
            float v = psc[mi][half];
            v += __shfl_xor_sync(0xffffffffu, v, 1);
            v += __shfl_xor_sync(0xffffffffu, v, 2);
            int r = wm * 32 + mi * 16 + g + half * 8;
            if (t4 == 0 && r < ne) s_part[r * 2 + wn] = v;
        }
    __syncthreads();

    if (t < ne) {
        float score = (s_part[t * 2 + 0] + s_part[t * 2 + 1]) + bv2[0];
        float sig = 1.0f / (1.0f + expf(-score));
        atomicMax((int*)&g_signal[s_src[t]], __float_as_int(sig));
    }
}

// ---------------- final: pred = H@W2 + b2 (+signal), labels ------------------
__global__ __launch_bounds__(256) void final_kernel(
    const float* __restrict__ W2, const float* __restrict__ b2,
    const float* __restrict__ ecw, const int* __restrict__ y,
    const int* __restrict__ bs_ptr, float* __restrict__ out,
    int out_size, int N)
{
    int bs = *bs_ptr; if (bs > N) bs = N;
    int row  = (blockIdx.x * blockDim.x + threadIdx.x) >> 5;
    int lane = threadIdx.x & 31;
    if (row >= bs) return;

    float4 hv  = *(const float4*)(g_H + (size_t)row * 128 + lane * 4);
    float4 w01 = *(const float4*)(W2 + lane * 8);
    float4 w23 = *(const float4*)(W2 + lane * 8 + 4);
    float d0 = hv.x * w01.x + hv.y * w01.z + hv.z * w23.x + hv.w * w23.z;
    float d1 = hv.x * w01.y + hv.y * w01.w + hv.z * w23.y + hv.w * w23.w;
    #pragma unroll
    for (int off = 16; off >= 1; off >>= 1) {
        d0 += __shfl_xor_sync(0xffffffffu, d0, off);
        d1 += __shfl_xor_sync(0xffffffffu, d1, off);
    }
    if (lane == 0) {
        out[(size_t)row * 2 + 0] = d0 + b2[0];
        out[(size_t)row * 2 + 1] = d1 + b2[1] + (*ecw) * g_signal[row];
        if (out_size >= 3 * bs) {
            int lab = g_idx64 ? y[2 * row] : y[row];
            out[(size_t)2 * bs + row] = (float)lab;
        }
    }
}

// ---------------- launch -----------------------------------------------------
extern "C" void kernel_launch(void* const* d_in, const int* in_sizes, int n_in,
                              void* d_out, int out_size) {
    const float* x         = (const float*)d_in[0];
    const float* edge_attr = (const float*)d_in[1];
    const float* W1        = (const float*)d_in[2];
    const float* b1        = (const float*)d_in[3];
    const float* W2        = (const float*)d_in[4];
    const float* b2        = (const float*)d_in[5];
    const float* V1        = (const float*)d_in[6];
    const float* bv1       = (const float*)d_in[7];
    const float* V2        = (const float*)d_in[8];
    const float* bv2       = (const float*)d_in[9];
    const float* ecw       = (const float*)d_in[10];
    const int*   ei        = (const int*)d_in[11];
    const int*   y         = (const int*)d_in[12];
    const int*   bs_ptr    = (const int*)d_in[13];
    float* out = (float*)d_out;

    int N = in_sizes[0] / 128;
    int E = in_sizes[1] / 128;

    int xg_smem = (128 * AST + 128 * BST) * 4;          // ~104.4 KB
    int eg_smem = (128 * AST + 2 * 64 * BST) * 4;       // ~104.4 KB
    cudaFuncSetAttribute(xgemm_mma, cudaFuncAttributeMaxDynamicSharedMemorySize, xg_smem);
    cudaFuncSetAttribute(edge_mma,  cudaFuncAttributeMaxDynamicSharedMemorySize, eg_smem);

    init_kernel<<<(N + 255) / 256, 256>>>(N, ei);
    compact_kernel<<<(E + 255) / 256, 256>>>(ei, E, bs_ptr);

    dim3 gx((N + 127) / 128, 14);
    xgemm_mma<<<gx, 256, xg_smem>>>(x, V1, W1, b1, N, bs_ptr);

    edge_mma<<<(E + 127) / 128, 256, eg_smem>>>(edge_attr, V1, bv1, V2, bv2, ei, E);

    final_kernel<<<(N * 32 + 255) / 256, 256>>>(W2, b2, ecw, y, bs_ptr, out, out_size, N);
}

// round 5
// speedup vs baseline: 1.2333x; 1.2333x over previous
#include <cuda_runtime.h>
#include <cuda_bf16.h>
#include <math.h>

#define NMAX 100000
#define EMAX 500000
#define KBW  264           // per-kblk A stride in words (256 + 8 pad)
#define AWM  (16 * KBW)    // per-warp-row-block A words (4224)
#define AWORDS (4 * AWM)   // 16896 words = 67.6KB

// ---------------- scratch ----------------------------------------------------
__device__ __align__(16) __nv_bfloat16 g_XAB[(size_t)NMAX * 768]; // [XA|XB] bf16
__device__ __align__(16) float g_H[(size_t)NMAX * 128];
__device__ __align__(16) unsigned g_Wp[20 * 16 * 512];   // permuted tf32 weights
__device__ float g_signal[NMAX];
__device__ int   g_elist[EMAX];
__device__ int   g_ecount;
__device__ int   g_idx64;

// ---------------- helpers -----------------------------------------------------
__device__ __forceinline__ unsigned f2tf(float f) {
    unsigned u; asm("cvt.rna.tf32.f32 %0, %1;" : "=r"(u) : "f"(f)); return u;
}
__device__ __forceinline__ void mma8(float* c, unsigned a0, unsigned a1,
                                     unsigned a2, unsigned a3,
                                     unsigned b0, unsigned b1) {
    asm volatile(
        "mma.sync.aligned.m16n8k8.row.col.f32.tf32.tf32.f32 "
        "{%0,%1,%2,%3},{%4,%5,%6,%7},{%8,%9},{%0,%1,%2,%3};"
        : "+f"(c[0]), "+f"(c[1]), "+f"(c[2]), "+f"(c[3])
        : "r"(a0), "r"(a1), "r"(a2), "r"(a3), "r"(b0), "r"(b1));
}
__device__ __forceinline__ void cp16(void* sdst, const void* gsrc) {
    unsigned s = (unsigned)__cvta_generic_to_shared(sdst);
    asm volatile("cp.async.cg.shared.global [%0], [%1], 16;\n" :: "r"(s), "l"(gsrc));
}
__device__ __forceinline__ void cp_commit() { asm volatile("cp.async.commit_group;\n" ::); }
__device__ __forceinline__ void cp_wait0()  { asm volatile("cp.async.wait_group 0;\n" ::); }
__device__ __forceinline__ void cp_wait1()  { asm volatile("cp.async.wait_group 1;\n" ::); }

// A permuted position: value A[r,k] -> word offset inside As
__device__ __forceinline__ int apos(int r, int k) {
    int wm = r >> 5, mi = (r >> 4) & 1, jbit = (r >> 3) & 1, g = r & 7;
    int kblk = k >> 3, kk = (k >> 2) & 1, t4 = k & 3;
    return wm * AWM + kblk * KBW + mi * 128 + (4 * g + t4) * 4 + (kk * 2 + jbit);
}

// ---------------- prep: permute+convert weights to tf32 ----------------------
// tiles: 0..5 V1[0:128], 6..11 V1[128:256], 12..13 W1, 14..19 V1[256:384]
__global__ void prep_kernel(const float* __restrict__ V1, const float* __restrict__ W1) {
    int idx = blockIdx.x * blockDim.x + threadIdx.x;
    if (idx >= 20 * 8192) return;
    int tile = idx >> 13;
    int rem  = idx & 8191;
    int kblk = rem >> 9;
    int p    = rem & 511;
    int wn   = p >> 8;
    int half = (p >> 7) & 1;
    int lane = (p >> 2) & 31;
    int j    = p & 3;
    int g = lane >> 2, t4 = lane & 3;
    int ni = half * 2 + (j >> 1);
    int kk = j & 1;
    int k = kblk * 8 + t4 + kk * 4;
    int n = wn * 32 + ni * 8 + g;
    float v;
    if (tile < 6)        v = V1[(size_t)k * 384 + tile * 64 + n];
    else if (tile < 12)  v = V1[(size_t)(128 + k) * 384 + (tile - 6) * 64 + n];
    else if (tile < 14)  v = W1[(size_t)k * 128 + (tile - 12) * 64 + n];
    else                 v = V1[(size_t)(256 + k) * 384 + (tile - 14) * 64 + n];
    g_Wp[idx] = f2tf(v);
}

// ---------------- init / compact ---------------------------------------------
__global__ void init_kernel(int N, const int* __restrict__ ei_raw) {
    int i = blockIdx.x * blockDim.x + threadIdx.x;
    if (i == 0) {
        g_ecount = 0;
        int allz = 1;
        #pragma unroll
        for (int j = 1; j < 64; j += 2)
            if (ei_raw[j] != 0) { allz = 0; break; }
        g_idx64 = allz;
    }
    if (i < N) g_signal[i] = 0.0f;
}

__global__ void compact_kernel(const int* __restrict__ ei, int E,
                               const int* __restrict__ bs_ptr) {
    int e = blockIdx.x * blockDim.x + threadIdx.x;
    if (e >= E) return;
    int bs  = *bs_ptr;
    int src = g_idx64 ? ei[2 * e] : ei[e];
    if (src < bs) {
        int p = atomicAdd(&g_ecount, 1);
        g_elist[p] = e;
    }
}

// ---------------- fused x-GEMM: x @ [V1a | V1b | W1], M=128 ------------------
__global__ __launch_bounds__(256) void xgemm_mma(
    const float* __restrict__ x, const float* __restrict__ b1,
    int N, const int* __restrict__ bs_ptr)
{
    extern __shared__ unsigned usm[];
    unsigned* As = usm;               // permuted tf32, AWORDS
    unsigned* Bs = usm + AWORDS;      // [16 kblk][512] permuted tf32

    int bs = *bs_ptr; if (bs > N) bs = N;
    int ct = blockIdx.y;
    int limit = (ct >= 6 && ct < 12) ? N : bs;
    int row0 = blockIdx.x * 128;
    if (row0 >= limit) return;
    int ne = min(128, limit - row0);
    int t = threadIdx.x;

    // B: contiguous cp.async from permuted weights
    for (int i = t; i < 2048; i += 256)
        cp16(&Bs[i * 4], &g_Wp[ct * 8192 + i * 4]);
    cp_commit();

    // A: gather + convert + permute
    for (int i = t; i < 4096; i += 256) {
        int r = i >> 5, c4 = i & 31;
        int rs = (r < ne) ? (row0 + r) : row0;
        float4 v = *(const float4*)(x + (size_t)rs * 128 + c4 * 4);
        int k0 = c4 * 4;
        As[apos(r, k0 + 0)] = f2tf(v.x);
        As[apos(r, k0 + 1)] = f2tf(v.y);
        As[apos(r, k0 + 2)] = f2tf(v.z);
        As[apos(r, k0 + 3)] = f2tf(v.w);
    }
    cp_wait0();
    __syncthreads();

    int lane = t & 31, w = t >> 5;
    int wm = w >> 1, wn = w & 1;
    int g = lane >> 2, t4 = lane & 3;
    float C[2][4][4] = {};

    const unsigned* Ap = As + wm * AWM + lane * 4;
    const unsigned* Bp = Bs + wn * 256 + lane * 4;

    #pragma unroll
    for (int kblk = 0; kblk < 16; kblk++) {
        uint4 a0 = *(const uint4*)(Ap + kblk * KBW);
        uint4 a1 = *(const uint4*)(Ap + kblk * KBW + 128);
        uint4 b0 = *(const uint4*)(Bp + kblk * 512);
        uint4 b1 = *(const uint4*)(Bp + kblk * 512 + 128);
        mma8(C[0][0], a0.x, a0.y, a0.z, a0.w, b0.x, b0.y);
        mma8(C[0][1], a0.x, a0.y, a0.z, a0.w, b0.z, b0.w);
        mma8(C[0][2], a0.x, a0.y, a0.z, a0.w, b1.x, b1.y);
        mma8(C[0][3], a0.x, a0.y, a0.z, a0.w, b1.z, b1.w);
        mma8(C[1][0], a1.x, a1.y, a1.z, a1.w, b0.x, b0.y);
        mma8(C[1][1], a1.x, a1.y, a1.z, a1.w, b0.z, b0.w);
        mma8(C[1][2], a1.x, a1.y, a1.z, a1.w, b1.x, b1.y);
        mma8(C[1][3], a1.x, a1.y, a1.z, a1.w, b1.z, b1.w);
    }

    bool isH = (ct >= 12);
    #pragma unroll
    for (int mi = 0; mi < 2; mi++)
        #pragma unroll
        for (int ni = 0; ni < 4; ni++) {
            int ncl = wn * 32 + ni * 8 + 2 * t4;
            #pragma unroll
            for (int half = 0; half < 2; half++) {
                int r = wm * 32 + mi * 16 + g + half * 8;
                if (r < ne) {
                    float v0 = C[mi][ni][half * 2 + 0];
                    float v1 = C[mi][ni][half * 2 + 1];
                    size_t row = row0 + r;
                    if (isH) {
                        int jg = (ct - 12) * 64 + ncl;
                        float2 o;
                        o.x = fmaxf(v0 + b1[jg],     0.f);
                        o.y = fmaxf(v1 + b1[jg + 1], 0.f);
                        *(float2*)(g_H + row * 128 + jg) = o;
                    } else {
                        int jg = ct * 64 + ncl;
                        __nv_bfloat162 o = __floats2bfloat162_rn(v0, v1);
                        *reinterpret_cast<__nv_bfloat162*>(g_XAB + row * 768 + jg) = o;
                    }
                }
            }
        }
}

// ---------------- edge kernel: 128 edges/block, chunked pipeline -------------
__global__ __launch_bounds__(256, 2) void edge_mma(
    const float* __restrict__ edge_attr,
    const float* __restrict__ bv1, const float* __restrict__ V2,
    const float* __restrict__ bv2, const int* __restrict__ ei, int E)
{
    extern __shared__ unsigned usm[];
    unsigned* As  = usm;                 // permuted tf32 (persistent)
    unsigned* Bb0 = usm + AWORDS;        // [8 kblk][512] chunk buffers
    unsigned* Bb1 = Bb0 + 4096;

    __shared__ int s_src[128], s_dst[128], s_eid[128];
    __shared__ float s_part[128 * 2];

    int cnt = g_ecount;
    int base = blockIdx.x * 128;
    if (base >= cnt) return;
    int ne = min(128, cnt - base);
    int t = threadIdx.x;
    int i64 = g_idx64;

    if (t < 128) {
        int e = 0, ss = 0, dd = 0;
        if (t < ne) {
            e  = g_elist[base + t];
            ss = i64 ? ei[2 * e]       : ei[e];
            dd = i64 ? ei[2 * (E + e)] : ei[E + e];
        }
        s_eid[t] = e; s_src[t] = ss; s_dst[t] = dd;
    }
    s_part[t] = 0.f;
    __syncthreads();

    // kick off chunk (ct=0, phase 0)
    for (int i = t; i < 1024; i += 256)
        cp16(&Bb0[i * 4], &g_Wp[14 * 8192 + i * 4]);
    cp_commit();

    // As: gather + convert + permute
    for (int i = t; i < 4096; i += 256) {
        int r = i >> 5, c4 = i & 31;
        float4 v = *(const float4*)(edge_attr + (size_t)s_eid[r] * 128 + c4 * 4);
        int k0 = c4 * 4;
        As[apos(r, k0 + 0)] = f2tf(v.x);
        As[apos(r, k0 + 1)] = f2tf(v.y);
        As[apos(r, k0 + 2)] = f2tf(v.z);
        As[apos(r, k0 + 3)] = f2tf(v.w);
    }

    int lane = t & 31, w = t >> 5;
    int wm = w >> 1, wn = w & 1;
    int g = lane >> 2, t4 = lane & 3;
    float psc[2][2] = {};

    const unsigned* Ap  = As + wm * AWM + lane * 4;
    const unsigned* B0p = Bb0 + wn * 256 + lane * 4;
    const unsigned* B1p = Bb1 + wn * 256 + lane * 4;

    #pragma unroll 1
    for (int ct = 0; ct < 6; ++ct) {
        // ---- phase 0: kblk 0..7 from Bb0; prefetch phase 1 into Bb1 ----
        __syncthreads();
        for (int i = t; i < 1024; i += 256)
            cp16(&Bb1[i * 4], &g_Wp[(14 + ct) * 8192 + 4096 + i * 4]);
        cp_commit();
        cp_wait1();
        __syncthreads();

        // prefetch bf16 XA/XB epilogue values for this ct
        unsigned pxa[2][2][4], pxb[2][2][4];
        #pragma unroll
        for (int mi = 0; mi < 2; mi++)
            #pragma unroll
            for (int half = 0; half < 2; half++) {
                int r = wm * 32 + mi * 16 + g + half * 8;
                const __nv_bfloat16* pa = g_XAB + (size_t)s_src[r] * 768 + ct * 64;
                const __nv_bfloat16* pb = g_XAB + (size_t)s_dst[r] * 768 + 384 + ct * 64;
                #pragma unroll
                for (int ni = 0; ni < 4; ni++) {
                    int ncl = wn * 32 + ni * 8 + 2 * t4;
                    pxa[mi][half][ni] = *reinterpret_cast<const unsigned*>(pa + ncl);
                    pxb[mi][half][ni] = *reinterpret_cast<const unsigned*>(pb + ncl);
                }
            }

        float C[2][4][4] = {};
        #pragma unroll
        for (int kb = 0; kb < 8; kb++) {
            uint4 a0 = *(const uint4*)(Ap + kb * KBW);
            uint4 a1 = *(const uint4*)(Ap + kb * KBW + 128);
            uint4 b0 = *(const uint4*)(B0p + kb * 512);
            uint4 b1 = *(const uint4*)(B0p + kb * 512 + 128);
            mma8(C[0][0], a0.x, a0.y, a0.z, a0.w, b0.x, b0.y);
            mma8(C[0][1], a0.x, a0.y, a0.z, a0.w, b0.z, b0.w);
            mma8(C[0][2], a0.x, a0.y, a0.z, a0.w, b1.x, b1.y);
            mma8(C[0][3], a0.x, a0.y, a0.z, a0.w, b1.z, b1.w);
            mma8(C[1][0], a1.x, a1.y, a1.z, a1.w, b0.x, b0.y);
            mma8(C[1][1], a1.x, a1.y, a1.z, a1.w, b0.z, b0.w);
            mma8(C[1][2], a1.x, a1.y, a1.z, a1.w, b1.x, b1.y);
            mma8(C[1][3], a1.x, a1.y, a1.z, a1.w, b1.z, b1.w);
        }

        // ---- phase 1: kblk 8..15 from Bb1; prefetch (ct+1, phase 0) ----
        __syncthreads();
        if (ct < 5) {
            for (int i = t; i < 1024; i += 256)
                cp16(&Bb0[i * 4], &g_Wp[(15 + ct) * 8192 + i * 4]);
        }
        cp_commit();
        cp_wait1();
        __syncthreads();

        #pragma unroll
        for (int kb = 0; kb < 8; kb++) {
            uint4 a0 = *(const uint4*)(Ap + (kb + 8) * KBW);
            uint4 a1 = *(const uint4*)(Ap + (kb + 8) * KBW + 128);
            uint4 b0 = *(const uint4*)(B1p + kb * 512);
            uint4 b1 = *(const uint4*)(B1p + kb * 512 + 128);
            mma8(C[0][0], a0.x, a0.y, a0.z, a0.w, b0.x, b0.y);
            mma8(C[0][1], a0.x, a0.y, a0.z, a0.w, b0.z, b0.w);
            mma8(C[0][2], a0.x, a0.y, a0.z, a0.w, b1.x, b1.y);
            mma8(C[0][3], a0.x, a0.y, a0.z, a0.w, b1.z, b1.w);
            mma8(C[1][0], a1.x, a1.y, a1.z, a1.w, b0.x, b0.y);
            mma8(C[1][1], a1.x, a1.y, a1.z, a1.w, b0.z, b0.w);
            mma8(C[1][2], a1.x, a1.y, a1.z, a1.w, b1.x, b1.y);
            mma8(C[1][3], a1.x, a1.y, a1.z, a1.w, b1.z, b1.w);
        }

        // ---- epilogue for this ct ----
        #pragma unroll
        for (int mi = 0; mi < 2; mi++)
            #pragma unroll
            for (int half = 0; half < 2; half++) {
                int r = wm * 32 + mi * 16 + g + half * 8;
                if (r < ne) {
                    #pragma unroll
                    for (int ni = 0; ni < 4; ni++) {
                        int ncl = wn * 32 + ni * 8 + 2 * t4;
                        int jg  = ct * 64 + ncl;
                        float2 bv = *(const float2*)(bv1 + jg);
                        float2 v2 = *(const float2*)(V2 + jg);
                        float2 fa = __bfloat1622float2(
                            *reinterpret_cast<__nv_bfloat162*>(&pxa[mi][half][ni]));
                        float2 fb = __bfloat1622float2(
                            *reinterpret_cast<__nv_bfloat162*>(&pxb[mi][half][ni]));
                        float h0 = fmaxf(C[mi][ni][half * 2 + 0] + fa.x + fb.x + bv.x, 0.f);
                        float h1 = fmaxf(C[mi][ni][half * 2 + 1] + fa.y + fb.y + bv.y, 0.f);
                        psc[mi][half] += h0 * v2.x + h1 * v2.y;
                    }
                }
            }
    }

    // deterministic per-edge reduction
    #pragma unroll
    for (int mi = 0; mi < 2; mi++)
        #pragma unroll
        for (int half = 0; half < 2; half++) {
            float v = psc[mi][half];
            v += __shfl_xor_sync(0xffffffffu, v, 1);
            v += __shfl_xor_sync(0xffffffffu, v, 2);
            int r = wm * 32 + mi * 16 + g + half * 8;
            if (t4 == 0 && r < ne) s_part[r * 2 + wn] = v;
        }
    __syncthreads();

    if (t < ne) {
        float score = (s_part[t * 2 + 0] + s_part[t * 2 + 1]) + bv2[0];
        float sig = 1.0f / (1.0f + expf(-score));
        atomicMax((int*)&g_signal[s_src[t]], __float_as_int(sig));
    }
}

// ---------------- final: pred = H@W2 + b2 (+signal), labels ------------------
__global__ __launch_bounds__(256) void final_kernel(
    const float* __restrict__ W2, const float* __restrict__ b2,
    const float* __restrict__ ecw, const int* __restrict__ y,
    const int* __restrict__ bs_ptr, float* __restrict__ out,
    int out_size, int N)
{
    int bs = *bs_ptr; if (bs > N) bs = N;
    int row  = (blockIdx.x * blockDim.x + threadIdx.x) >> 5;
    int lane = threadIdx.x & 31;
    if (row >= bs) return;

    float4 hv  = *(const float4*)(g_H + (size_t)row * 128 + lane * 4);
    float4 w01 = *(const float4*)(W2 + lane * 8);
    float4 w23 = *(const float4*)(W2 + lane * 8 + 4);
    float d0 = hv.x * w01.x + hv.y * w01.z + hv.z * w23.x + hv.w * w23.z;
    float d1 = hv.x * w01.y + hv.y * w01.w + hv.z * w23.y + hv.w * w23.w;
    #pragma unroll
    for (int off = 16; off >= 1; off >>= 1) {
        d0 += __shfl_xor_sync(0xffffffffu, d0, off);
        d1 += __shfl_xor_sync(0xffffffffu, d1, off);
    }
    if (lane == 0) {
        out[(size_t)row * 2 + 0] = d0 + b2[0];
        out[(size_t)row * 2 + 1] = d1 + b2[1] + (*ecw) * g_signal[row];
        if (out_size >= 3 * bs) {
            int lab = g_idx64 ? y[2 * row] : y[row];
            out[(size_t)2 * bs + row] = (float)lab;
        }
    }
}

// ---------------- launch -----------------------------------------------------
extern "C" void kernel_launch(void* const* d_in, const int* in_sizes, int n_in,
                              void* d_out, int out_size) {
    const float* x         = (const float*)d_in[0];
    const float* edge_attr = (const float*)d_in[1];
    const float* W1        = (const float*)d_in[2];
    const float* b1        = (const float*)d_in[3];
    const float* W2        = (const float*)d_in[4];
    const float* b2        = (const float*)d_in[5];
    const float* V1        = (const float*)d_in[6];
    const float* bv1       = (const float*)d_in[7];
    const float* V2        = (const float*)d_in[8];
    const float* bv2       = (const float*)d_in[9];
    const float* ecw       = (const float*)d_in[10];
    const int*   ei        = (const int*)d_in[11];
    const int*   y         = (const int*)d_in[12];
    const int*   bs_ptr    = (const int*)d_in[13];
    float* out = (float*)d_out;

    int N = in_sizes[0] / 128;
    int E = in_sizes[1] / 128;

    int xg_smem = (AWORDS + 16 * 512) * 4;          // ~100.4 KB
    int eg_smem = (AWORDS + 2 * 8 * 512) * 4;       // ~100.4 KB
    cudaFuncSetAttribute(xgemm_mma, cudaFuncAttributeMaxDynamicSharedMemorySize, xg_smem);
    cudaFuncSetAttribute(edge_mma,  cudaFuncAttributeMaxDynamicSharedMemorySize, eg_smem);

    prep_kernel<<<(20 * 8192 + 255) / 256, 256>>>(V1, W1);
    init_kernel<<<(N + 255) / 256, 256>>>(N, ei);
    compact_kernel<<<(E + 255) / 256, 256>>>(ei, E, bs_ptr);

    dim3 gx((N + 127) / 128, 14);
    xgemm_mma<<<gx, 256, xg_smem>>>(x, b1, N, bs_ptr);

    edge_mma<<<(E + 127) / 128, 256, eg_smem>>>(edge_attr, bv1, V2, bv2, ei, E);

    final_kernel<<<(N * 32 + 255) / 256, 256>>>(W2, b2, ecw, y, bs_ptr, out, out_size, N);
}

// round 6
// speedup vs baseline: 1.4716x; 1.1932x over previous
#include <cuda_runtime.h>
#include <cuda_bf16.h>
#include <math.h>

#define NMAX 100000
#define EMAX 500000
#define KBW  264           // per-kblk A stride in words (256 + 8 pad)
#define AWM  (16 * KBW)    // per-warp-row-block A words (4224)
#define AWORDS (4 * AWM)   // 16896 words = 67.6KB

// ---------------- scratch ----------------------------------------------------
__device__ __align__(16) __nv_bfloat16 g_XAB[(size_t)NMAX * 768]; // [XA|XB] bf16
__device__ __align__(16) float g_H[(size_t)NMAX * 128];
__device__ __align__(16) unsigned g_Wp[20 * 16 * 512];   // permuted tf32 weights
__device__ float g_signal[NMAX];
__device__ int   g_elist[EMAX];
__device__ int   g_ecount;
__device__ int   g_idx64;

// ---------------- helpers -----------------------------------------------------
__device__ __forceinline__ unsigned f2tf(float f) {
    unsigned u; asm("cvt.rna.tf32.f32 %0, %1;" : "=r"(u) : "f"(f)); return u;
}
__device__ __forceinline__ void mma8(float* c, unsigned a0, unsigned a1,
                                     unsigned a2, unsigned a3,
                                     unsigned b0, unsigned b1) {
    asm volatile(
        "mma.sync.aligned.m16n8k8.row.col.f32.tf32.tf32.f32 "
        "{%0,%1,%2,%3},{%4,%5,%6,%7},{%8,%9},{%0,%1,%2,%3};"
        : "+f"(c[0]), "+f"(c[1]), "+f"(c[2]), "+f"(c[3])
        : "r"(a0), "r"(a1), "r"(a2), "r"(a3), "r"(b0), "r"(b1));
}
__device__ __forceinline__ void cp16(void* sdst, const void* gsrc) {
    unsigned s = (unsigned)__cvta_generic_to_shared(sdst);
    asm volatile("cp.async.cg.shared.global [%0], [%1], 16;\n" :: "r"(s), "l"(gsrc));
}
__device__ __forceinline__ void cp_commit() { asm volatile("cp.async.commit_group;\n" ::); }
__device__ __forceinline__ void cp_wait1()  { asm volatile("cp.async.wait_group 1;\n" ::); }

// A permuted position: value A[r,k] -> word offset inside As
__device__ __forceinline__ int apos(int r, int k) {
    int wm = r >> 5, mi = (r >> 4) & 1, jbit = (r >> 3) & 1, g = r & 7;
    int kblk = k >> 3, kk = (k >> 2) & 1, t4 = k & 3;
    return wm * AWM + kblk * KBW + mi * 128 + (4 * g + t4) * 4 + (kk * 2 + jbit);
}

// ---------------- prep: permute+convert weights to tf32 ----------------------
// tiles: 0..5 V1[0:128], 6..11 V1[128:256], 12..13 W1, 14..19 V1[256:384]
__global__ void prep_kernel(const float* __restrict__ V1, const float* __restrict__ W1) {
    int idx = blockIdx.x * blockDim.x + threadIdx.x;
    if (idx >= 20 * 8192) return;
    int tile = idx >> 13;
    int rem  = idx & 8191;
    int kblk = rem >> 9;
    int p    = rem & 511;
    int wn   = p >> 8;
    int half = (p >> 7) & 1;
    int lane = (p >> 2) & 31;
    int j    = p & 3;
    int g = lane >> 2, t4 = lane & 3;
    int ni = half * 2 + (j >> 1);
    int kk = j & 1;
    int k = kblk * 8 + t4 + kk * 4;
    int n = wn * 32 + ni * 8 + g;
    float v;
    if (tile < 6)        v = V1[(size_t)k * 384 + tile * 64 + n];
    else if (tile < 12)  v = V1[(size_t)(128 + k) * 384 + (tile - 6) * 64 + n];
    else if (tile < 14)  v = W1[(size_t)k * 128 + (tile - 12) * 64 + n];
    else                 v = V1[(size_t)(256 + k) * 384 + (tile - 14) * 64 + n];
    g_Wp[idx] = f2tf(v);
}

// ---------------- init / compact ---------------------------------------------
__global__ void init_kernel(int N, const int* __restrict__ ei_raw) {
    int i = blockIdx.x * blockDim.x + threadIdx.x;
    if (i == 0) {
        g_ecount = 0;
        int allz = 1;
        #pragma unroll
        for (int j = 1; j < 64; j += 2)
            if (ei_raw[j] != 0) { allz = 0; break; }
        g_idx64 = allz;
    }
    if (i < N) g_signal[i] = 0.0f;
}

__global__ void compact_kernel(const int* __restrict__ ei, int E,
                               const int* __restrict__ bs_ptr) {
    int e = blockIdx.x * blockDim.x + threadIdx.x;
    if (e >= E) return;
    int bs  = *bs_ptr;
    int src = g_idx64 ? ei[2 * e] : ei[e];
    if (src < bs) {
        int p = atomicAdd(&g_ecount, 1);
        g_elist[p] = e;
    }
}

// ---------------- fused x-GEMM: persistent A, loop over ct tiles -------------
// rows < bs: tiles 0..13 ; rows >= bs: tiles 6..11 (XB only)
__global__ __launch_bounds__(256, 2) void xgemm_mma(
    const float* __restrict__ x, const float* __restrict__ b1,
    int N, const int* __restrict__ bs_ptr)
{
    extern __shared__ unsigned usm[];
    unsigned* As  = usm;                 // permuted tf32 (persistent)
    unsigned* Bb0 = usm + AWORDS;        // [8 kblk][512] chunk buffers
    unsigned* Bb1 = Bb0 + 4096;

    int bs = *bs_ptr; if (bs > N) bs = N;
    int row0 = blockIdx.x * 128;
    if (row0 >= N) return;
    int ne = min(128, N - row0);
    int t = threadIdx.x;

    int tbase  = (row0 < bs) ? 0 : 6;
    int ntiles = (row0 < bs) ? 14 : 6;

    // kick off chunk (tile0, phase 0)
    for (int i = t; i < 1024; i += 256)
        cp16(&Bb0[i * 4], &g_Wp[tbase * 8192 + i * 4]);
    cp_commit();

    // A: load + convert + permute (once)
    for (int i = t; i < 4096; i += 256) {
        int r = i >> 5, c4 = i & 31;
        int rs = (r < ne) ? (row0 + r) : row0;
        float4 v = *(const float4*)(x + (size_t)rs * 128 + c4 * 4);
        int k0 = c4 * 4;
        As[apos(r, k0 + 0)] = f2tf(v.x);
        As[apos(r, k0 + 1)] = f2tf(v.y);
        As[apos(r, k0 + 2)] = f2tf(v.z);
        As[apos(r, k0 + 3)] = f2tf(v.w);
    }

    int lane = t & 31, w = t >> 5;
    int wm = w >> 1, wn = w & 1;
    int g = lane >> 2, t4 = lane & 3;

    const unsigned* Ap  = As + wm * AWM + lane * 4;
    const unsigned* B0p = Bb0 + wn * 256 + lane * 4;
    const unsigned* B1p = Bb1 + wn * 256 + lane * 4;

    #pragma unroll 1
    for (int ti = 0; ti < ntiles; ++ti) {
        int ct = tbase + ti;
        // ---- phase 0: kblk 0..7 from Bb0; prefetch phase 1 into Bb1 ----
        __syncthreads();
        for (int i = t; i < 1024; i += 256)
            cp16(&Bb1[i * 4], &g_Wp[ct * 8192 + 4096 + i * 4]);
        cp_commit();
        cp_wait1();
        __syncthreads();

        float C[2][4][4] = {};
        #pragma unroll
        for (int kb = 0; kb < 8; kb++) {
            uint4 a0 = *(const uint4*)(Ap + kb * KBW);
            uint4 a1 = *(const uint4*)(Ap + kb * KBW + 128);
            uint4 b0 = *(const uint4*)(B0p + kb * 512);
            uint4 b1 = *(const uint4*)(B0p + kb * 512 + 128);
            mma8(C[0][0], a0.x, a0.y, a0.z, a0.w, b0.x, b0.y);
            mma8(C[0][1], a0.x, a0.y, a0.z, a0.w, b0.z, b0.w);
            mma8(C[0][2], a0.x, a0.y, a0.z, a0.w, b1.x, b1.y);
            mma8(C[0][3], a0.x, a0.y, a0.z, a0.w, b1.z, b1.w);
            mma8(C[1][0], a1.x, a1.y, a1.z, a1.w, b0.x, b0.y);
            mma8(C[1][1], a1.x, a1.y, a1.z, a1.w, b0.z, b0.w);
            mma8(C[1][2], a1.x, a1.y, a1.z, a1.w, b1.x, b1.y);
            mma8(C[1][3], a1.x, a1.y, a1.z, a1.w, b1.z, b1.w);
        }

        // ---- phase 1: kblk 8..15 from Bb1; prefetch (ti+1, phase 0) ----
        __syncthreads();
        if (ti + 1 < ntiles) {
            for (int i = t; i < 1024; i += 256)
                cp16(&Bb0[i * 4], &g_Wp[(ct + 1) * 8192 + i * 4]);
        }
        cp_commit();
        cp_wait1();
        __syncthreads();

        #pragma unroll
        for (int kb = 0; kb < 8; kb++) {
            uint4 a0 = *(const uint4*)(Ap + (kb + 8) * KBW);
            uint4 a1 = *(const uint4*)(Ap + (kb + 8) * KBW + 128);
            uint4 b0 = *(const uint4*)(B1p + kb * 512);
            uint4 b1 = *(const uint4*)(B1p + kb * 512 + 128);
            mma8(C[0][0], a0.x, a0.y, a0.z, a0.w, b0.x, b0.y);
            mma8(C[0][1], a0.x, a0.y, a0.z, a0.w, b0.z, b0.w);
            mma8(C[0][2], a0.x, a0.y, a0.z, a0.w, b1.x, b1.y);
            mma8(C[0][3], a0.x, a0.y, a0.z, a0.w, b1.z, b1.w);
            mma8(C[1][0], a1.x, a1.y, a1.z, a1.w, b0.x, b0.y);
            mma8(C[1][1], a1.x, a1.y, a1.z, a1.w, b0.z, b0.w);
            mma8(C[1][2], a1.x, a1.y, a1.z, a1.w, b1.x, b1.y);
            mma8(C[1][3], a1.x, a1.y, a1.z, a1.w, b1.z, b1.w);
        }

        // ---- epilogue for this ct ----
        bool isH = (ct >= 12);
        int mlim = (ct >= 6 && ct < 12) ? ne : min(ne, bs - row0);
        #pragma unroll
        for (int mi = 0; mi < 2; mi++)
            #pragma unroll
            for (int ni = 0; ni < 4; ni++) {
                int ncl = wn * 32 + ni * 8 + 2 * t4;
                #pragma unroll
                for (int half = 0; half < 2; half++) {
                    int r = wm * 32 + mi * 16 + g + half * 8;
                    if (r < mlim) {
                        float v0 = C[mi][ni][half * 2 + 0];
                        float v1 = C[mi][ni][half * 2 + 1];
                        size_t row = row0 + r;
                        if (isH) {
                            int jg = (ct - 12) * 64 + ncl;
                            float2 o;
                            o.x = fmaxf(v0 + b1[jg],     0.f);
                            o.y = fmaxf(v1 + b1[jg + 1], 0.f);
                            *(float2*)(g_H + row * 128 + jg) = o;
                        } else {
                            int jg = ct * 64 + ncl;   // 0..767 (XA then XB)
                            __nv_bfloat162 o = __floats2bfloat162_rn(v0, v1);
                            *reinterpret_cast<__nv_bfloat162*>(g_XAB + row * 768 + jg) = o;
                        }
                    }
                }
            }
    }
}

// ---------------- edge kernel: 128 edges/block, chunked pipeline -------------
__global__ __launch_bounds__(256, 2) void edge_mma(
    const float* __restrict__ edge_attr,
    const float* __restrict__ bv1, const float* __restrict__ V2,
    const float* __restrict__ bv2, const int* __restrict__ ei, int E)
{
    extern __shared__ unsigned usm[];
    unsigned* As  = usm;                 // permuted tf32 (persistent)
    unsigned* Bb0 = usm + AWORDS;        // [8 kblk][512] chunk buffers
    unsigned* Bb1 = Bb0 + 4096;

    __shared__ int s_src[128], s_dst[128], s_eid[128];
    __shared__ float s_part[128 * 2];

    int cnt = g_ecount;
    int base = blockIdx.x * 128;
    if (base >= cnt) return;
    int ne = min(128, cnt - base);
    int t = threadIdx.x;
    int i64 = g_idx64;

    if (t < 128) {
        int e = 0, ss = 0, dd = 0;
        if (t < ne) {
            e  = g_elist[base + t];
            ss = i64 ? ei[2 * e]       : ei[e];
            dd = i64 ? ei[2 * (E + e)] : ei[E + e];
        }
        s_eid[t] = e; s_src[t] = ss; s_dst[t] = dd;
    }
    s_part[t] = 0.f;
    __syncthreads();

    // kick off chunk (ct=0, phase 0)
    for (int i = t; i < 1024; i += 256)
        cp16(&Bb0[i * 4], &g_Wp[14 * 8192 + i * 4]);
    cp_commit();

    // As: gather + convert + permute
    for (int i = t; i < 4096; i += 256) {
        int r = i >> 5, c4 = i & 31;
        float4 v = *(const float4*)(edge_attr + (size_t)s_eid[r] * 128 + c4 * 4);
        int k0 = c4 * 4;
        As[apos(r, k0 + 0)] = f2tf(v.x);
        As[apos(r, k0 + 1)] = f2tf(v.y);
        As[apos(r, k0 + 2)] = f2tf(v.z);
        As[apos(r, k0 + 3)] = f2tf(v.w);
    }

    int lane = t & 31, w = t >> 5;
    int wm = w >> 1, wn = w & 1;
    int g = lane >> 2, t4 = lane & 3;
    float psc[2][2] = {};

    const unsigned* Ap  = As + wm * AWM + lane * 4;
    const unsigned* B0p = Bb0 + wn * 256 + lane * 4;
    const unsigned* B1p = Bb1 + wn * 256 + lane * 4;

    #pragma unroll 1
    for (int ct = 0; ct < 6; ++ct) {
        // ---- phase 0: kblk 0..7 from Bb0; prefetch phase 1 into Bb1 ----
        __syncthreads();
        for (int i = t; i < 1024; i += 256)
            cp16(&Bb1[i * 4], &g_Wp[(14 + ct) * 8192 + 4096 + i * 4]);
        cp_commit();
        cp_wait1();
        __syncthreads();

        // prefetch bf16 XA/XB epilogue values for this ct
        unsigned pxa[2][2][4], pxb[2][2][4];
        #pragma unroll
        for (int mi = 0; mi < 2; mi++)
            #pragma unroll
            for (int half = 0; half < 2; half++) {
                int r = wm * 32 + mi * 16 + g + half * 8;
                const __nv_bfloat16* pa = g_XAB + (size_t)s_src[r] * 768 + ct * 64;
                const __nv_bfloat16* pb = g_XAB + (size_t)s_dst[r] * 768 + 384 + ct * 64;
                #pragma unroll
                for (int ni = 0; ni < 4; ni++) {
                    int ncl = wn * 32 + ni * 8 + 2 * t4;
                    pxa[mi][half][ni] = *reinterpret_cast<const unsigned*>(pa + ncl);
                    pxb[mi][half][ni] = *reinterpret_cast<const unsigned*>(pb + ncl);
                }
            }

        float C[2][4][4] = {};
        #pragma unroll
        for (int kb = 0; kb < 8; kb++) {
            uint4 a0 = *(const uint4*)(Ap + kb * KBW);
            uint4 a1 = *(const uint4*)(Ap + kb * KBW + 128);
            uint4 b0 = *(const uint4*)(B0p + kb * 512);
            uint4 b1 = *(const uint4*)(B0p + kb * 512 + 128);
            mma8(C[0][0], a0.x, a0.y, a0.z, a0.w, b0.x, b0.y);
            mma8(C[0][1], a0.x, a0.y, a0.z, a0.w, b0.z, b0.w);
            mma8(C[0][2], a0.x, a0.y, a0.z, a0.w, b1.x, b1.y);
            mma8(C[0][3], a0.x, a0.y, a0.z, a0.w, b1.z, b1.w);
            mma8(C[1][0], a1.x, a1.y, a1.z, a1.w, b0.x, b0.y);
            mma8(C[1][1], a1.x, a1.y, a1.z, a1.w, b0.z, b0.w);
            mma8(C[1][2], a1.x, a1.y, a1.z, a1.w, b1.x, b1.y);
            mma8(C[1][3], a1.x, a1.y, a1.z, a1.w, b1.z, b1.w);
        }

        // ---- phase 1: kblk 8..15 from Bb1; prefetch (ct+1, phase 0) ----
        __syncthreads();
        if (ct < 5) {
            for (int i = t; i < 1024; i += 256)
                cp16(&Bb0[i * 4], &g_Wp[(15 + ct) * 8192 + i * 4]);
        }
        cp_commit();
        cp_wait1();
        __syncthreads();

        #pragma unroll
        for (int kb = 0; kb < 8; kb++) {
            uint4 a0 = *(const uint4*)(Ap + (kb + 8) * KBW);
            uint4 a1 = *(const uint4*)(Ap + (kb + 8) * KBW + 128);
            uint4 b0 = *(const uint4*)(B1p + kb * 512);
            uint4 b1 = *(const uint4*)(B1p + kb * 512 + 128);
            mma8(C[0][0], a0.x, a0.y, a0.z, a0.w, b0.x, b0.y);
            mma8(C[0][1], a0.x, a0.y, a0.z, a0.w, b0.z, b0.w);
            mma8(C[0][2], a0.x, a0.y, a0.z, a0.w, b1.x, b1.y);
            mma8(C[0][3], a0.x, a0.y, a0.z, a0.w, b1.z, b1.w);
            mma8(C[1][0], a1.x, a1.y, a1.z, a1.w, b0.x, b0.y);
            mma8(C[1][1], a1.x, a1.y, a1.z, a1.w, b0.z, b0.w);
            mma8(C[1][2], a1.x, a1.y, a1.z, a1.w, b1.x, b1.y);
            mma8(C[1][3], a1.x, a1.y, a1.z, a1.w, b1.z, b1.w);
        }

        // ---- epilogue for this ct ----
        #pragma unroll
        for (int mi = 0; mi < 2; mi++)
            #pragma unroll
            for (int half = 0; half < 2; half++) {
                int r = wm * 32 + mi * 16 + g + half * 8;
                if (r < ne) {
                    #pragma unroll
                    for (int ni = 0; ni < 4; ni++) {
                        int ncl = wn * 32 + ni * 8 + 2 * t4;
                        int jg  = ct * 64 + ncl;
                        float2 bv = *(const float2*)(bv1 + jg);
                        float2 v2 = *(const float2*)(V2 + jg);
                        float2 fa = __bfloat1622float2(
                            *reinterpret_cast<__nv_bfloat162*>(&pxa[mi][half][ni]));
                        float2 fb = __bfloat1622float2(
                            *reinterpret_cast<__nv_bfloat162*>(&pxb[mi][half][ni]));
                        float h0 = fmaxf(C[mi][ni][half * 2 + 0] + fa.x + fb.x + bv.x, 0.f);
                        float h1 = fmaxf(C[mi][ni][half * 2 + 1] + fa.y + fb.y + bv.y, 0.f);
                        psc[mi][half] += h0 * v2.x + h1 * v2.y;
                    }
                }
            }
    }

    // deterministic per-edge reduction
    #pragma unroll
    for (int mi = 0; mi < 2; mi++)
        #pragma unroll
        for (int half = 0; half < 2; half++) {
            float v = psc[mi][half];
            v += __shfl_xor_sync(0xffffffffu, v, 1);
            v += __shfl_xor_sync(0xffffffffu, v, 2);
            int r = wm * 32 + mi * 16 + g + half * 8;
            if (t4 == 0 && r < ne) s_part[r * 2 + wn] = v;
        }
    __syncthreads();

    if (t < ne) {
        float score = (s_part[t * 2 + 0] + s_part[t * 2 + 1]) + bv2[0];
        float sig = 1.0f / (1.0f + expf(-score));
        atomicMax((int*)&g_signal[s_src[t]], __float_as_int(sig));
    }
}

// ---------------- final: pred = H@W2 + b2 (+signal), labels ------------------
__global__ __launch_bounds__(256) void final_kernel(
    const float* __restrict__ W2, const float* __restrict__ b2,
    const float* __restrict__ ecw, const int* __restrict__ y,
    const int* __restrict__ bs_ptr, float* __restrict__ out,
    int out_size, int N)
{
    int bs = *bs_ptr; if (bs > N) bs = N;
    int row  = (blockIdx.x * blockDim.x + threadIdx.x) >> 5;
    int lane = threadIdx.x & 31;
    if (row >= bs) return;

    float4 hv  = *(const float4*)(g_H + (size_t)row * 128 + lane * 4);
    float4 w01 = *(const float4*)(W2 + lane * 8);
    float4 w23 = *(const float4*)(W2 + lane * 8 + 4);
    float d0 = hv.x * w01.x + hv.y * w01.z + hv.z * w23.x + hv.w * w23.z;
    float d1 = hv.x * w01.y + hv.y * w01.w + hv.z * w23.y + hv.w * w23.w;
    #pragma unroll
    for (int off = 16; off >= 1; off >>= 1) {
        d0 += __shfl_xor_sync(0xffffffffu, d0, off);
        d1 += __shfl_xor_sync(0xffffffffu, d1, off);
    }
    if (lane == 0) {
        out[(size_t)row * 2 + 0] = d0 + b2[0];
        out[(size_t)row * 2 + 1] = d1 + b2[1] + (*ecw) * g_signal[row];
        if (out_size >= 3 * bs) {
            int lab = g_idx64 ? y[2 * row] : y[row];
            out[(size_t)2 * bs + row] = (float)lab;
        }
    }
}

// ---------------- launch -----------------------------------------------------
extern "C" void kernel_launch(void* const* d_in, const int* in_sizes, int n_in,
                              void* d_out, int out_size) {
    const float* x         = (const float*)d_in[0];
    const float* edge_attr = (const float*)d_in[1];
    const float* W1        = (const float*)d_in[2];
    const float* b1        = (const float*)d_in[3];
    const float* W2        = (const float*)d_in[4];
    const float* b2        = (const float*)d_in[5];
    const float* V1        = (const float*)d_in[6];
    const float* bv1       = (const float*)d_in[7];
    const float* V2        = (const float*)d_in[8];
    const float* bv2       = (const float*)d_in[9];
    const float* ecw       = (const float*)d_in[10];
    const int*   ei        = (const int*)d_in[11];
    const int*   y         = (const int*)d_in[12];
    const int*   bs_ptr    = (const int*)d_in[13];
    float* out = (float*)d_out;

    int N = in_sizes[0] / 128;
    int E = in_sizes[1] / 128;

    int gm_smem = (AWORDS + 2 * 8 * 512) * 4;       // ~100.4 KB (both GEMMs)
    cudaFuncSetAttribute(xgemm_mma, cudaFuncAttributeMaxDynamicSharedMemorySize, gm_smem);
    cudaFuncSetAttribute(edge_mma,  cudaFuncAttributeMaxDynamicSharedMemorySize, gm_smem);

    prep_kernel<<<(20 * 8192 + 255) / 256, 256>>>(V1, W1);
    init_kernel<<<(N + 255) / 256, 256>>>(N, ei);
    compact_kernel<<<(E + 255) / 256, 256>>>(ei, E, bs_ptr);

    xgemm_mma<<<(N + 127) / 128, 256, gm_smem>>>(x, b1, N, bs_ptr);

    edge_mma<<<(E + 127) / 128, 256, gm_smem>>>(edge_attr, bv1, V2, bv2, ei, E);

    final_kernel<<<(N * 32 + 255) / 256, 256>>>(W2, b2, ecw, y, bs_ptr, out, out_size, N);
}

// round 7
// speedup vs baseline: 1.9637x; 1.3344x over previous
#include <cuda_runtime.h>
#include <cuda_fp16.h>
#include <math.h>

#define NMAX 100000
#define EMAX 500000
#define AWORDS 8192      // A tile: 128 rows x 128 k fp16, permuted (32KB)
#define BWORDS 4096      // B tile: 128 k x 64 n fp16, permuted (16KB)

// ---------------- scratch ----------------------------------------------------
__device__ __align__(16) __half g_XAB[(size_t)NMAX * 768];   // [XA|XB] fp16
__device__ __align__(16) float g_H[(size_t)NMAX * 128];
__device__ __align__(16) unsigned g_Wp[20 * BWORDS];         // permuted fp16 weights
__device__ float g_signal[NMAX];
__device__ int   g_elist[EMAX];
__device__ int   g_ecount;
__device__ int   g_idx64;

// ---------------- helpers -----------------------------------------------------
__device__ __forceinline__ void mma16(float* c, uint4 a, unsigned b0, unsigned b1) {
    asm volatile(
        "mma.sync.aligned.m16n8k16.row.col.f32.f16.f16.f32 "
        "{%0,%1,%2,%3},{%4,%5,%6,%7},{%8,%9},{%0,%1,%2,%3};"
        : "+f"(c[0]), "+f"(c[1]), "+f"(c[2]), "+f"(c[3])
        : "r"(a.x), "r"(a.y), "r"(a.z), "r"(a.w), "r"(b0), "r"(b1));
}
__device__ __forceinline__ void cp16(void* sdst, const void* gsrc) {
    unsigned s = (unsigned)__cvta_generic_to_shared(sdst);
    asm volatile("cp.async.cg.shared.global [%0], [%1], 16;\n" :: "r"(s), "l"(gsrc));
}
__device__ __forceinline__ void cp_commit() { asm volatile("cp.async.commit_group;\n" ::); }
__device__ __forceinline__ void cp_wait1()  { asm volatile("cp.async.wait_group 1;\n" ::); }
__device__ __forceinline__ unsigned h2bits(__half2 h) {
    return *reinterpret_cast<unsigned*>(&h);
}

// A permuted word position for even k (holds pair k,k+1)
__device__ __forceinline__ int apos16(int r, int k) {
    int wm = r >> 5, mi = (r >> 4) & 1, jbit = (r >> 3) & 1, g = r & 7;
    int kblk = k >> 4, khalf = (k >> 3) & 1, t4 = (k >> 1) & 3;
    return ((wm * 8 + kblk) * 2 + mi) * 128 + (g * 4 + t4) * 4 + khalf * 2 + jbit;
}

// ---------------- prep: permute+convert weights to fp16 ----------------------
// tiles: 0..5 V1[0:128], 6..11 V1[128:256], 12..13 W1, 14..19 V1[256:384]
__global__ void prep_kernel(const float* __restrict__ V1, const float* __restrict__ W1) {
    int idx = blockIdx.x * blockDim.x + threadIdx.x;
    if (idx >= 20 * BWORDS) return;
    int tile = idx >> 12;
    int rem  = idx & 4095;
    int kblk = rem >> 9;
    int wn   = (rem >> 8) & 1;
    int h    = (rem >> 7) & 1;
    int lane = (rem >> 2) & 31;
    int nlow = (rem >> 1) & 1;
    int khalf = rem & 1;
    int g = lane >> 2, t4 = lane & 3;
    int ni = 2 * h + nlow;
    int n  = wn * 32 + ni * 8 + g;
    int k  = kblk * 16 + khalf * 8 + t4 * 2;
    float va, vb;
    if (tile < 6) {
        va = V1[(size_t)k * 384 + tile * 64 + n];
        vb = V1[(size_t)(k + 1) * 384 + tile * 64 + n];
    } else if (tile < 12) {
        va = V1[(size_t)(128 + k) * 384 + (tile - 6) * 64 + n];
        vb = V1[(size_t)(129 + k) * 384 + (tile - 6) * 64 + n];
    } else if (tile < 14) {
        va = W1[(size_t)k * 128 + (tile - 12) * 64 + n];
        vb = W1[(size_t)(k + 1) * 128 + (tile - 12) * 64 + n];
    } else {
        va = V1[(size_t)(256 + k) * 384 + (tile - 14) * 64 + n];
        vb = V1[(size_t)(257 + k) * 384 + (tile - 14) * 64 + n];
    }
    g_Wp[idx] = h2bits(__floats2half2_rn(va, vb));
}

// ---------------- init / compact ---------------------------------------------
__global__ void init_kernel(int N, const int* __restrict__ ei_raw) {
    int i = blockIdx.x * blockDim.x + threadIdx.x;
    if (i == 0) {
        g_ecount = 0;
        int allz = 1;
        #pragma unroll
        for (int j = 1; j < 64; j += 2)
            if (ei_raw[j] != 0) { allz = 0; break; }
        g_idx64 = allz;
    }
    if (i < N) g_signal[i] = 0.0f;
}

__global__ void compact_kernel(const int* __restrict__ ei, int E,
                               const int* __restrict__ bs_ptr) {
    int e = blockIdx.x * blockDim.x + threadIdx.x;
    if (e >= E) return;
    int bs  = *bs_ptr;
    int src = g_idx64 ? ei[2 * e] : ei[e];
    if (src < bs) {
        int p = atomicAdd(&g_ecount, 1);
        g_elist[p] = e;
    }
}

// ---------------- fused x-GEMM: persistent A, loop over ct tiles -------------
__global__ __launch_bounds__(256, 2) void xgemm_mma(
    const float* __restrict__ x, const float* __restrict__ b1,
    int N, const int* __restrict__ bs_ptr)
{
    extern __shared__ unsigned usm[];
    unsigned* As  = usm;                 // AWORDS (persistent)
    unsigned* Bb0 = usm + AWORDS;        // BWORDS each
    unsigned* Bb1 = Bb0 + BWORDS;

    int bs = *bs_ptr; if (bs > N) bs = N;
    int row0 = blockIdx.x * 128;
    if (row0 >= N) return;
    int ne = min(128, N - row0);
    int t = threadIdx.x;

    int tbase  = (row0 < bs) ? 0 : 6;
    int ntiles = (row0 < bs) ? 14 : 6;

    // kick off B tile 0
    for (int i = t; i < BWORDS / 4; i += 256)
        cp16(&Bb0[i * 4], &g_Wp[tbase * BWORDS + i * 4]);
    cp_commit();

    // A: load + convert + permute (once)
    for (int i = t; i < 4096; i += 256) {
        int r = i >> 5, c4 = i & 31;
        int rs = (r < ne) ? (row0 + r) : row0;
        float4 v = *(const float4*)(x + (size_t)rs * 128 + c4 * 4);
        int k0 = c4 * 4;
        As[apos16(r, k0)]     = h2bits(__floats2half2_rn(v.x, v.y));
        As[apos16(r, k0 + 2)] = h2bits(__floats2half2_rn(v.z, v.w));
    }

    int lane = t & 31, w = t >> 5;
    int wm = w >> 1, wn = w & 1;
    int g = lane >> 2, t4 = lane & 3;

    const uint4* Au = (const uint4*)As;

    #pragma unroll 1
    for (int ti = 0; ti < ntiles; ++ti) {
        int ct = tbase + ti;
        const uint4* Bu = (const uint4*)((ti & 1) ? Bb1 : Bb0);
        unsigned* Bn = (ti & 1) ? Bb0 : Bb1;

        __syncthreads();                     // readers of Bn (tile ti-1) done
        if (ti + 1 < ntiles) {
            for (int i = t; i < BWORDS / 4; i += 256)
                cp16(&Bn[i * 4], &g_Wp[(ct + 1) * BWORDS + i * 4]);
        }
        cp_commit();
        cp_wait1();                          // tile ti ready
        __syncthreads();

        float C[2][4][4] = {};
        #pragma unroll
        for (int kb = 0; kb < 8; kb++) {
            uint4 a0 = Au[((wm * 8 + kb) * 2 + 0) * 32 + lane];
            uint4 a1 = Au[((wm * 8 + kb) * 2 + 1) * 32 + lane];
            uint4 b0 = Bu[((kb * 2 + wn) * 2 + 0) * 32 + lane];
            uint4 b1 = Bu[((kb * 2 + wn) * 2 + 1) * 32 + lane];
            mma16(C[0][0], a0, b0.x, b0.y);
            mma16(C[0][1], a0, b0.z, b0.w);
            mma16(C[0][2], a0, b1.x, b1.y);
            mma16(C[0][3], a0, b1.z, b1.w);
            mma16(C[1][0], a1, b0.x, b0.y);
            mma16(C[1][1], a1, b0.z, b0.w);
            mma16(C[1][2], a1, b1.x, b1.y);
            mma16(C[1][3], a1, b1.z, b1.w);
        }

        // ---- epilogue for this ct ----
        bool isH = (ct >= 12);
        int mlim = (ct >= 6 && ct < 12) ? ne : min(ne, bs - row0);
        #pragma unroll
        for (int mi = 0; mi < 2; mi++)
            #pragma unroll
            for (int ni = 0; ni < 4; ni++) {
                int ncl = wn * 32 + ni * 8 + 2 * t4;
                #pragma unroll
                for (int half = 0; half < 2; half++) {
                    int r = wm * 32 + mi * 16 + g + half * 8;
                    if (r < mlim) {
                        float v0 = C[mi][ni][half * 2 + 0];
                        float v1 = C[mi][ni][half * 2 + 1];
                        size_t row = row0 + r;
                        if (isH) {
                            int jg = (ct - 12) * 64 + ncl;
                            float2 o;
                            o.x = fmaxf(v0 + b1[jg],     0.f);
                            o.y = fmaxf(v1 + b1[jg + 1], 0.f);
                            *(float2*)(g_H + row * 128 + jg) = o;
                        } else {
                            int jg = ct * 64 + ncl;   // 0..767 (XA then XB)
                            __half2 o = __floats2half2_rn(v0, v1);
                            *reinterpret_cast<__half2*>(g_XAB + row * 768 + jg) = o;
                        }
                    }
                }
            }
    }
}

// ---------------- edge kernel: 128 edges/block, double-buffered B ------------
__global__ __launch_bounds__(256, 2) void edge_mma(
    const float* __restrict__ edge_attr,
    const float* __restrict__ bv1, const float* __restrict__ V2,
    const float* __restrict__ bv2, const int* __restrict__ ei, int E)
{
    extern __shared__ unsigned usm[];
    unsigned* As  = usm;
    unsigned* Bb0 = usm + AWORDS;
    unsigned* Bb1 = Bb0 + BWORDS;

    __shared__ int s_src[128], s_dst[128], s_eid[128];
    __shared__ float s_part[128 * 2];

    int cnt = g_ecount;
    int base = blockIdx.x * 128;
    if (base >= cnt) return;
    int ne = min(128, cnt - base);
    int t = threadIdx.x;
    int i64 = g_idx64;

    if (t < 128) {
        int e = 0, ss = 0, dd = 0;
        if (t < ne) {
            e  = g_elist[base + t];
            ss = i64 ? ei[2 * e]       : ei[e];
            dd = i64 ? ei[2 * (E + e)] : ei[E + e];
        }
        s_eid[t] = e; s_src[t] = ss; s_dst[t] = dd;
    }
    s_part[t] = 0.f;
    __syncthreads();

    // kick off B tile (ct=0 → weight tile 14)
    for (int i = t; i < BWORDS / 4; i += 256)
        cp16(&Bb0[i * 4], &g_Wp[14 * BWORDS + i * 4]);
    cp_commit();

    // As: gather + convert + permute
    for (int i = t; i < 4096; i += 256) {
        int r = i >> 5, c4 = i & 31;
        float4 v = *(const float4*)(edge_attr + (size_t)s_eid[r] * 128 + c4 * 4);
        int k0 = c4 * 4;
        As[apos16(r, k0)]     = h2bits(__floats2half2_rn(v.x, v.y));
        As[apos16(r, k0 + 2)] = h2bits(__floats2half2_rn(v.z, v.w));
    }

    int lane = t & 31, w = t >> 5;
    int wm = w >> 1, wn = w & 1;
    int g = lane >> 2, t4 = lane & 3;
    float psc[2][2] = {};

    const uint4* Au = (const uint4*)As;

    #pragma unroll 1
    for (int ct = 0; ct < 6; ++ct) {
        const uint4* Bu = (const uint4*)((ct & 1) ? Bb1 : Bb0);
        unsigned* Bn = (ct & 1) ? Bb0 : Bb1;

        __syncthreads();
        if (ct < 5) {
            for (int i = t; i < BWORDS / 4; i += 256)
                cp16(&Bn[i * 4], &g_Wp[(15 + ct) * BWORDS + i * 4]);
        }
        cp_commit();
        cp_wait1();
        __syncthreads();

        // prefetch fp16 XA/XB epilogue values for this ct
        unsigned pxa[2][2][4], pxb[2][2][4];
        #pragma unroll
        for (int mi = 0; mi < 2; mi++)
            #pragma unroll
            for (int half = 0; half < 2; half++) {
                int r = wm * 32 + mi * 16 + g + half * 8;
                const __half* pa = g_XAB + (size_t)s_src[r] * 768 + ct * 64;
                const __half* pb = g_XAB + (size_t)s_dst[r] * 768 + 384 + ct * 64;
                #pragma unroll
                for (int ni = 0; ni < 4; ni++) {
                    int ncl = wn * 32 + ni * 8 + 2 * t4;
                    pxa[mi][half][ni] = *reinterpret_cast<const unsigned*>(pa + ncl);
                    pxb[mi][half][ni] = *reinterpret_cast<const unsigned*>(pb + ncl);
                }
            }

        float C[2][4][4] = {};
        #pragma unroll
        for (int kb = 0; kb < 8; kb++) {
            uint4 a0 = Au[((wm * 8 + kb) * 2 + 0) * 32 + lane];
            uint4 a1 = Au[((wm * 8 + kb) * 2 + 1) * 32 + lane];
            uint4 b0 = Bu[((kb * 2 + wn) * 2 + 0) * 32 + lane];
            uint4 b1 = Bu[((kb * 2 + wn) * 2 + 1) * 32 + lane];
            mma16(C[0][0], a0, b0.x, b0.y);
            mma16(C[0][1], a0, b0.z, b0.w);
            mma16(C[0][2], a0, b1.x, b1.y);
            mma16(C[0][3], a0, b1.z, b1.w);
            mma16(C[1][0], a1, b0.x, b0.y);
            mma16(C[1][1], a1, b0.z, b0.w);
            mma16(C[1][2], a1, b1.x, b1.y);
            mma16(C[1][3], a1, b1.z, b1.w);
        }

        // ---- epilogue for this ct ----
        #pragma unroll
        for (int mi = 0; mi < 2; mi++)
            #pragma unroll
            for (int half = 0; half < 2; half++) {
                int r = wm * 32 + mi * 16 + g + half * 8;
                if (r < ne) {
                    #pragma unroll
                    for (int ni = 0; ni < 4; ni++) {
                        int ncl = wn * 32 + ni * 8 + 2 * t4;
                        int jg  = ct * 64 + ncl;
                        float2 bv = *(const float2*)(bv1 + jg);
                        float2 v2 = *(const float2*)(V2 + jg);
                        float2 fa = __half22float2(
                            *reinterpret_cast<__half2*>(&pxa[mi][half][ni]));
                        float2 fb = __half22float2(
                            *reinterpret_cast<__half2*>(&pxb[mi][half][ni]));
                        float h0 = fmaxf(C[mi][ni][half * 2 + 0] + fa.x + fb.x + bv.x, 0.f);
                        float h1 = fmaxf(C[mi][ni][half * 2 + 1] + fa.y + fb.y + bv.y, 0.f);
                        psc[mi][half] += h0 * v2.x + h1 * v2.y;
                    }
                }
            }
    }

    // deterministic per-edge reduction
    #pragma unroll
    for (int mi = 0; mi < 2; mi++)
        #pragma unroll
        for (int half = 0; half < 2; half++) {
            float v = psc[mi][half];
            v += __shfl_xor_sync(0xffffffffu, v, 1);
            v += __shfl_xor_sync(0xffffffffu, v, 2);
            int r = wm * 32 + mi * 16 + g + half * 8;
            if (t4 == 0 && r < ne) s_part[r * 2 + wn] = v;
        }
    __syncthreads();

    if (t < ne) {
        float score = (s_part[t * 2 + 0] + s_part[t * 2 + 1]) + bv2[0];
        float sig = 1.0f / (1.0f + expf(-score));
        atomicMax((int*)&g_signal[s_src[t]], __float_as_int(sig));
    }
}

// ---------------- final: pred = H@W2 + b2 (+signal), labels ------------------
__global__ __launch_bounds__(256) void final_kernel(
    const float* __restrict__ W2, const float* __restrict__ b2,
    const float* __restrict__ ecw, const int* __restrict__ y,
    const int* __restrict__ bs_ptr, float* __restrict__ out,
    int out_size, int N)
{
    int bs = *bs_ptr; if (bs > N) bs = N;
    int row  = (blockIdx.x * blockDim.x + threadIdx.x) >> 5;
    int lane = threadIdx.x & 31;
    if (row >= bs) return;

    float4 hv  = *(const float4*)(g_H + (size_t)row * 128 + lane * 4);
    float4 w01 = *(const float4*)(W2 + lane * 8);
    float4 w23 = *(const float4*)(W2 + lane * 8 + 4);
    float d0 = hv.x * w01.x + hv.y * w01.z + hv.z * w23.x + hv.w * w23.z;
    float d1 = hv.x * w01.y + hv.y * w01.w + hv.z * w23.y + hv.w * w23.w;
    #pragma unroll
    for (int off = 16; off >= 1; off >>= 1) {
        d0 += __shfl_xor_sync(0xffffffffu, d0, off);
        d1 += __shfl_xor_sync(0xffffffffu, d1, off);
    }
    if (lane == 0) {
        out[(size_t)row * 2 + 0] = d0 + b2[0];
        out[(size_t)row * 2 + 1] = d1 + b2[1] + (*ecw) * g_signal[row];
        if (out_size >= 3 * bs) {
            int lab = g_idx64 ? y[2 * row] : y[row];
            out[(size_t)2 * bs + row] = (float)lab;
        }
    }
}

// ---------------- launch -----------------------------------------------------
extern "C" void kernel_launch(void* const* d_in, const int* in_sizes, int n_in,
                              void* d_out, int out_size) {
    const float* x         = (const float*)d_in[0];
    const float* edge_attr = (const float*)d_in[1];
    const float* W1        = (const float*)d_in[2];
    const float* b1        = (const float*)d_in[3];
    const float* W2        = (const float*)d_in[4];
    const float* b2        = (const float*)d_in[5];
    const float* V1        = (const float*)d_in[6];
    const float* bv1       = (const float*)d_in[7];
    const float* V2        = (const float*)d_in[8];
    const float* bv2       = (const float*)d_in[9];
    const float* ecw       = (const float*)d_in[10];
    const int*   ei        = (const int*)d_in[11];
    const int*   y         = (const int*)d_in[12];
    const int*   bs_ptr    = (const int*)d_in[13];
    float* out = (float*)d_out;

    int N = in_sizes[0] / 128;
    int E = in_sizes[1] / 128;

    int gm_smem = (AWORDS + 2 * BWORDS) * 4;       // 64 KB (both GEMMs)
    cudaFuncSetAttribute(xgemm_mma, cudaFuncAttributeMaxDynamicSharedMemorySize, gm_smem);
    cudaFuncSetAttribute(edge_mma,  cudaFuncAttributeMaxDynamicSharedMemorySize, gm_smem);

    prep_kernel<<<(20 * BWORDS + 255) / 256, 256>>>(V1, W1);
    init_kernel<<<(N + 255) / 256, 256>>>(N, ei);
    compact_kernel<<<(E + 255) / 256, 256>>>(ei, E, bs_ptr);

    xgemm_mma<<<(N + 127) / 128, 256, gm_smem>>>(x, b1, N, bs_ptr);

    edge_mma<<<(E + 127) / 128, 256, gm_smem>>>(edge_attr, bv1, V2, bv2, ei, E);

    final_kernel<<<(N * 32 + 255) / 256, 256>>>(W2, b2, ecw, y, bs_ptr, out, out_size, N);
}